// round 1
// baseline (speedup 1.0000x reference)
#include <cuda_runtime.h>
#include <cuda_bf16.h>

// FlowNet correlation, B=4 C=256 H=W=128, 81 displacements (dy,dx in [-4,4]).
// out[b, dyi*9+dxi, y, x] = (1/C) * sum_c x1[b,c,y,x] * x2[b,c,y+dyi-4,x+dxi-4]
// (x2 zero-padded).
//
// Design: each block handles one batch, 4 output rows, full width W, and a
// group of 3 dy values. 128 threads; thread = (row r in 0..3, lane) owning 4
// consecutive pixels x0=4*lane. Accumulators: 3dy x 4px x 9dx = 108 fp32 regs.
// Channel loop staged 2 channels at a time through smem with a register
// prefetch double-buffer. Smem uses skew swizzle phys = idx + (idx>>2) so the
// stride-4-pixel window reads hit banks 5*lane+const -> conflict-free.

namespace {
constexpr int Bn = 4, Cn = 256, Hn = 128, Wn = 128;
constexpr int MD = 4;                 // max displacement
constexpr int NDY = 3;                // dy values fused per block
constexpr int TY = 4;                 // output rows per block
constexpr int ROWS = TY + NDY - 1;    // staged x2 rows = 6
constexpr int HALOW = Wn + 2 * MD;    // 136 staged columns
constexpr int SROW = 172;             // swizzled smem row stride (floats), >= 135+33+1
constexpr int CH = Hn * Wn;           // channel stride = 16384
}

__global__ __launch_bounds__(128, 2)
void corr_kernel(const float* __restrict__ x1,
                 const float* __restrict__ x2,
                 float* __restrict__ out)
{
    __shared__ float s2[2][ROWS * SROW];   // 2 channels staged per iteration

    const int tid  = threadIdx.x;
    const int lane = tid & 31;
    const int r    = tid >> 5;             // 0..3 : output row within tile
    const int d0   = blockIdx.x * NDY;     // 0,3,6 : first dy of this block's group
    const int y0   = blockIdx.y * TY;      // tile base output row
    const int b    = blockIdx.z;
    const int x0   = lane * 4;             // first pixel owned by this thread
    const int ysbase = y0 + d0 - MD;       // global row of staged tile row 0

    float acc[NDY * TY * 9];               // [dd][i][d]
    #pragma unroll
    for (int k = 0; k < NDY * TY * 9; k++) acc[k] = 0.0f;

    // prefetch staging registers (next 2 channels)
    float  sx2[2][2][5];
    float4 sx1[2];

    auto stage = [&](int c) {
        #pragma unroll
        for (int ch = 0; ch < 2; ++ch) {
            const float* p2 = x2 + (size_t)(b * Cn + c + ch) * CH;
            #pragma unroll
            for (int rr = 0; rr < 2; ++rr) {
                int row = r + rr * TY;                 // staged tile row
                int ys  = ysbase + row;                // global x2 row
                bool rok = (row < ROWS) & (ys >= 0) & (ys < Hn);
                int ysc = ys < 0 ? 0 : (ys > Hn - 1 ? Hn - 1 : ys);
                const float* prow = p2 + (size_t)ysc * Wn;
                #pragma unroll
                for (int j = 0; j < 5; ++j) {
                    int col = lane + 32 * j;           // staged column index
                    int gx  = col - MD;                // global x2 column
                    bool ok = rok & (col < HALOW) & (gx >= 0) & (gx < Wn);
                    int gxc = gx < 0 ? 0 : (gx > Wn - 1 ? Wn - 1 : gx);
                    sx2[ch][rr][j] = ok ? __ldg(prow + gxc) : 0.0f;
                }
            }
            sx1[ch] = __ldg((const float4*)(x1 + (size_t)(b * Cn + c + ch) * CH
                                               + (size_t)(y0 + r) * Wn + x0));
        }
    };

    stage(0);

    for (int c = 0; c < Cn; c += 2) {
        __syncthreads();   // previous smem fully consumed

        // store staged x2 to smem (skew swizzle: phys = col + (col>>2))
        #pragma unroll
        for (int ch = 0; ch < 2; ++ch)
            #pragma unroll
            for (int rr = 0; rr < 2; ++rr) {
                int row = r + rr * TY;
                #pragma unroll
                for (int j = 0; j < 5; ++j) {
                    int col = lane + 32 * j;
                    if (row < ROWS && col < HALOW)
                        s2[ch][row * SROW + col + (col >> 2)] = sx2[ch][rr][j];
                }
            }

        float a[2][4];
        #pragma unroll
        for (int ch = 0; ch < 2; ++ch) {
            a[ch][0] = sx1[ch].x; a[ch][1] = sx1[ch].y;
            a[ch][2] = sx1[ch].z; a[ch][3] = sx1[ch].w;
        }

        __syncthreads();   // smem tiles visible

        if (c + 2 < Cn) stage(c + 2);   // overlap next LDGs with compute

        #pragma unroll
        for (int ch = 0; ch < 2; ++ch) {
            #pragma unroll
            for (int dd = 0; dd < NDY; ++dd) {
                // window of 12 values for this (row, dy): stored idx x0+u,
                // phys = (r+dd)*SROW + 5*lane + u + (u>>2)  -> conflict-free
                float w[12];
                const float* sp = &s2[ch][(r + dd) * SROW + 5 * lane];
                #pragma unroll
                for (int u = 0; u < 12; ++u) w[u] = sp[u + (u >> 2)];
                #pragma unroll
                for (int i = 0; i < 4; ++i)
                    #pragma unroll
                    for (int d = 0; d < 9; ++d)
                        acc[(dd * 4 + i) * 9 + d] =
                            fmaf(a[ch][i], w[i + d], acc[(dd * 4 + i) * 9 + d]);
            }
        }
    }

    // epilogue: scale by 1/C and write (float4 per (dd,d))
    const float inv = 1.0f / (float)Cn;
    const int y = y0 + r;
    #pragma unroll
    for (int dd = 0; dd < NDY; ++dd)
        #pragma unroll
        for (int d = 0; d < 9; ++d) {
            int oc = (d0 + dd) * 9 + d;
            float4 o;
            o.x = acc[(dd * 4 + 0) * 9 + d] * inv;
            o.y = acc[(dd * 4 + 1) * 9 + d] * inv;
            o.z = acc[(dd * 4 + 2) * 9 + d] * inv;
            o.w = acc[(dd * 4 + 3) * 9 + d] * inv;
            *(float4*)(out + (((size_t)b * 81 + oc) * Hn + y) * Wn + x0) = o;
        }
}

extern "C" void kernel_launch(void* const* d_in, const int* in_sizes, int n_in,
                              void* d_out, int out_size)
{
    const float* x1 = (const float*)d_in[0];
    const float* x2 = (const float*)d_in[1];
    float* out = (float*)d_out;

    dim3 grid(9 / NDY, Hn / TY, Bn);   // (3, 32, 4) = 384 blocks
    corr_kernel<<<grid, 128>>>(x1, x2, out);
}

// round 3
// speedup vs baseline: 2.2054x; 2.2054x over previous
#include <cuda_runtime.h>
#include <cuda_bf16.h>

// FlowNet correlation, B=4 C=256 H=W=128, 81 displacements (dy,dx in [-4,4]).
// out[b, dyi*9+dxi, y, x] = (1/C) * sum_c x1[b,c,y,x] * x2pad[b,c,y+dyi,x+dxi]
//
// Design (Round 2/3):
//  - block = (dy group of 3) x (4 output rows) x batch; 128 threads.
//    thread (r=tid/32, lane) owns 4 consecutive pixels x0=4*lane of row y0+r.
//    acc: 3dy x 4px x 9dx = 108 fp32.
//  - ALL global->smem traffic via cp.async 16B granules into a 3-stage ring
//    (2 channels per stage). Zero padding via src-size 0 (zfill).
//  - smem layout granule-aligned (staged x2 row padded to 144 floats):
//    window read = 3x LDS.128 at 16B lane stride (conflict-free), x1 = 1x LDS.128.
//  - __launch_bounds__(128,3): 12 warps/SM, grid 384 fits in one wave (444 slots).

namespace {
constexpr int Bn = 4, Cn = 256, Hn = 128, Wn = 128, MD = 4;
constexpr int NDY = 3;                 // dy per block
constexpr int TY  = 4;                 // output rows per block
constexpr int ROWS = TY + NDY - 1;     // staged x2 rows = 6
constexpr int SROWF = 144;             // floats per staged x2 row (34 granules, padded)
constexpr int X2F = ROWS * SROWF;      // 864 floats
constexpr int X1F = TY * Wn;           // 512 floats
constexpr int CHF = X2F + X1F;         // 1376 floats per channel
constexpr int NSTG = 3;                // ring stages (2 channels each)
constexpr int CH = Hn * Wn;            // channel stride (elems)
constexpr int G2 = ROWS * 34;          // 204 x2 granules per channel
}

__device__ __forceinline__ void cpa16(unsigned dst, const void* src, unsigned sz) {
    asm volatile("cp.async.cg.shared.global [%0], [%1], 16, %2;\n"
                 :: "r"(dst), "l"(src), "r"(sz) : "memory");
}
__device__ __forceinline__ void cpa_commit() {
    asm volatile("cp.async.commit_group;\n" ::: "memory");
}
__device__ __forceinline__ void cpa_wait2() {
    asm volatile("cp.async.wait_group 2;\n" ::: "memory");
}

__global__ __launch_bounds__(128, 3)
void corr_kernel(const float* __restrict__ x1,
                 const float* __restrict__ x2,
                 float* __restrict__ out)
{
    __shared__ __align__(16) float sm[NSTG * 2 * CHF];   // 33 KB

    const int tid  = threadIdx.x;
    const int lane = tid & 31;
    const int r    = tid >> 5;             // 0..3
    const int d0   = blockIdx.x * NDY;     // first dy of group
    const int y0   = blockIdx.y * TY;
    const int b    = blockIdx.z;
    const int x0   = lane * 4;
    const int ysbase = y0 + d0 - MD;

    const unsigned sbase = (unsigned)__cvta_generic_to_shared(sm);

    // ---- per-thread cp.async descriptors (loop-invariant) ----
    // x2: granule g = tid (+128). granule covers staged cols [4gc,4gc+4) of
    // row g/34, i.e. global cols [4gc-4, 4gc). Interior granules (gc in
    // [1,32]) are 16B-aligned reads; edges/OOB rows zero-fill (src-size 0).
    int      goff2[2];
    unsigned sz2[2];
    unsigned sd2[2];
    bool     do2[2];
    #pragma unroll
    for (int k = 0; k < 2; ++k) {
        int g   = tid + 128 * k;
        int row = g / 34, gc = g - row * 34;
        int ys  = ysbase + row;
        bool ok = (g < G2) && (gc >= 1) && (gc <= 32) && (ys >= 0) && (ys < Hn);
        int ysc = min(max(ys, 0), Hn - 1);
        goff2[k] = ysc * Wn + (ok ? (4 * gc - 4) : 0);
        sz2[k]   = ok ? 16u : 0u;
        sd2[k]   = (unsigned)(row * SROWF + 4 * gc) * 4u;
        do2[k]   = (g < G2);
    }
    // x1: one granule per thread: row r, cols [x0, x0+4)
    const int      goff1 = (y0 + r) * Wn + x0;
    const unsigned sd1   = (unsigned)(X2F + r * Wn + x0) * 4u;

    const char* p2base = (const char*)(x2 + (size_t)(b * Cn) * CH);
    const char* p1base = (const char*)(x1 + (size_t)(b * Cn) * CH);

    auto issue_stage = [&](int it) {
        const int c0   = 2 * it;
        const unsigned slotb = sbase + (unsigned)((it % NSTG) * 2 * CHF) * 4u;
        #pragma unroll
        for (int ch = 0; ch < 2; ++ch) {
            const size_t cb = (size_t)(c0 + ch) * CH * 4u;
            const unsigned sb = slotb + (unsigned)(ch * CHF) * 4u;
            #pragma unroll
            for (int k = 0; k < 2; ++k)
                if (do2[k]) cpa16(sb + sd2[k], p2base + cb + (size_t)goff2[k] * 4u, sz2[k]);
            cpa16(sb + sd1, p1base + cb + (size_t)goff1 * 4u, 16u);
        }
    };

    float acc[NDY * TY * 9];
    #pragma unroll
    for (int k = 0; k < NDY * TY * 9; ++k) acc[k] = 0.0f;

    // ---- pipeline prologue: 2 stages in flight ----
    issue_stage(0); cpa_commit();
    issue_stage(1); cpa_commit();

    const int NIT = Cn / 2;   // 128
    for (int it = 0; it < NIT; ++it) {
        __syncthreads();                   // all threads done computing stage it-1
        if (it + 2 < NIT) issue_stage(it + 2);
        cpa_commit();                      // uniform group count (may be empty)
        cpa_wait2();                       // stage it complete (this thread)
        __syncthreads();                   // stage it visible to all

        const float* sp = sm + (it % NSTG) * 2 * CHF;
        #pragma unroll
        for (int ch = 0; ch < 2; ++ch) {
            const float* sc = sp + ch * CHF;
            const float4 av = *(const float4*)(sc + X2F + r * Wn + x0);
            const float a0 = av.x, a1 = av.y, a2 = av.z, a3 = av.w;
            #pragma unroll
            for (int dd = 0; dd < NDY; ++dd) {
                const float4* wp = (const float4*)(sc + (r + dd) * SROWF + x0);
                const float4 w0 = wp[0], w1 = wp[1], w2 = wp[2];
                const float w[12] = { w0.x, w0.y, w0.z, w0.w,
                                      w1.x, w1.y, w1.z, w1.w,
                                      w2.x, w2.y, w2.z, w2.w };
                float* ap = acc + dd * 36;
                #pragma unroll
                for (int d = 0; d < 9; ++d) {
                    ap[0 * 9 + d] = fmaf(a0, w[0 + d], ap[0 * 9 + d]);
                    ap[1 * 9 + d] = fmaf(a1, w[1 + d], ap[1 * 9 + d]);
                    ap[2 * 9 + d] = fmaf(a2, w[2 + d], ap[2 * 9 + d]);
                    ap[3 * 9 + d] = fmaf(a3, w[3 + d], ap[3 * 9 + d]);
                }
            }
        }
    }

    // ---- epilogue ----
    const float inv = 1.0f / (float)Cn;
    const int y = y0 + r;
    #pragma unroll
    for (int dd = 0; dd < NDY; ++dd)
        #pragma unroll
        for (int d = 0; d < 9; ++d) {
            const int oc = (d0 + dd) * 9 + d;
            float4 o;
            o.x = acc[(dd * 4 + 0) * 9 + d] * inv;
            o.y = acc[(dd * 4 + 1) * 9 + d] * inv;
            o.z = acc[(dd * 4 + 2) * 9 + d] * inv;
            o.w = acc[(dd * 4 + 3) * 9 + d] * inv;
            *(float4*)(out + (((size_t)b * 81 + oc) * Hn + y) * Wn + x0) = o;
        }
}

extern "C" void kernel_launch(void* const* d_in, const int* in_sizes, int n_in,
                              void* d_out, int out_size)
{
    const float* x1 = (const float*)d_in[0];
    const float* x2 = (const float*)d_in[1];
    float* out = (float*)d_out;

    dim3 grid(9 / NDY, Hn / TY, Bn);   // (3, 32, 4) = 384 blocks
    corr_kernel<<<grid, 128>>>(x1, x2, out);
}